// round 5
// baseline (speedup 1.0000x reference)
#include <cuda_runtime.h>
#include <cuda_fp16.h>
#include <cstdint>

#define OBS 128
#define NAGENT 16
#define HID 128
#define GE 256
#define LE 256
#define F1 512
#define F2 512
#define NACT 8
#define MAXB 2048
#define MAXM (MAXB * NAGENT)

// fp16 weight pack offsets (halves)
#define OFF_WCAT  0            // [128, 384] = [W_pre | W_loc]
#define OFF_WGCN  49152        // [2,128,128]
#define OFF_WPOST 81920        // [128,256]
#define OFF_W1    114688       // [512,512]
#define OFF_W2    376832       // [512,512]
#define WH_TOTAL  638976

__device__ __align__(16) __half g_wh[WH_TOTAL];
__device__ __align__(16) float  g_bcat[384];
__device__ __align__(16) __half g_xloc[MAXM * 384];   // [x | loc]
__device__ __align__(16) __half g_xbar[MAXB * HID];
__device__ __align__(16) __half g_s0[MAXB * HID];
__device__ __align__(16) __half g_s1[MAXB * HID];
__device__ __align__(16) __half g_gv[MAXB * GE];
__device__ __align__(16) float  g_G1[MAXB * F1];
__device__ __align__(16) __half g_z1[MAXM * F1];
__device__ __align__(16) __half g_z2[MAXM * F2];

#define BM 128
#define BN 128
#define BK 32

__device__ __forceinline__ void cp16(uint32_t dst, const void* src) {
    asm volatile("cp.async.cg.shared.global [%0], [%1], 16;\n" ::"r"(dst), "l"(src));
}
__device__ __forceinline__ uint32_t smem_u32(const void* p) {
    return (uint32_t)__cvta_generic_to_shared(p);
}

// ---------------------------------------------------------------------------
// fp16 HMMA GEMM: C[M,N] = epi(A[M,K] @ B[K,N]); A row stride lda.
// AF32: A is fp32 (converted on the fly). B fp16 row-major (stride N).
// epi: +bias[n], +rowAdd[(m>>4)*N+n], relu. Out fp16 (Ch) or fp32 (Cf).
// BM=BN=128, BK=32, 128 threads, 4 warps @ 64x64 tiles.
// M%128==0, N%128==0, K%32==0.
// ---------------------------------------------------------------------------
template <int AF32>
__global__ __launch_bounds__(128) void hgemm(
    const void* __restrict__ Ap, const __half* __restrict__ B,
    __half* __restrict__ Ch, float* __restrict__ Cf,
    int M, int N, int K, int lda,
    const float* __restrict__ bias, const float* __restrict__ rowAdd,
    int doRelu)
{
    __shared__ __half As[2][BM][BK + 8];
    __shared__ __half Bs[2][BK][BN + 8];

    const int tid  = threadIdx.x;
    const int lane = tid & 31;
    const int wid  = tid >> 5;
    const int wm   = wid >> 1;     // 0..1 (64-row slab)
    const int wn   = wid & 1;      // 0..1 (64-col slab)
    const int brow = blockIdx.y * BM;
    const int bcol = blockIdx.x * BN;

    const __half* Ah = (const __half*)Ap;
    const float*  Af = (const float*)Ap;

    float c[4][8][4];
#pragma unroll
    for (int i = 0; i < 4; i++)
#pragma unroll
        for (int j = 0; j < 8; j++)
#pragma unroll
            for (int e = 0; e < 4; e++) c[i][j][e] = 0.f;

    const int nT = K / BK;

    auto loadStage = [&](int t, int st) {
        const int k0 = t * BK;
        // A tile: 128x32 halves = 512 chunks of 8 halves; 4 chunks/thread
#pragma unroll
        for (int j = 0; j < 4; j++) {
            const int ch = j * 128 + tid;
            const int r = ch >> 2, cc = (ch & 3) * 8;
            if (AF32) {
                const float4* s =
                    (const float4*)(Af + (size_t)(brow + r) * lda + k0 + cc);
                float4 v0 = s[0], v1 = s[1];
                __half2 h0 = __floats2half2_rn(v0.x, v0.y);
                __half2 h1 = __floats2half2_rn(v0.z, v0.w);
                __half2 h2 = __floats2half2_rn(v1.x, v1.y);
                __half2 h3 = __floats2half2_rn(v1.z, v1.w);
                uint4 u;
                u.x = *(uint32_t*)&h0; u.y = *(uint32_t*)&h1;
                u.z = *(uint32_t*)&h2; u.w = *(uint32_t*)&h3;
                *(uint4*)&As[st][r][cc] = u;
            } else {
                cp16(smem_u32(&As[st][r][cc]),
                     Ah + (size_t)(brow + r) * lda + k0 + cc);
            }
        }
        // B tile: 32x128 halves = 512 chunks; 4 chunks/thread
#pragma unroll
        for (int j = 0; j < 4; j++) {
            const int ch = j * 128 + tid;
            const int r = ch >> 4, cc = (ch & 15) * 8;
            cp16(smem_u32(&Bs[st][r][cc]), B + (size_t)(k0 + r) * N + bcol + cc);
        }
    };

    loadStage(0, 0);
    asm volatile("cp.async.commit_group;\n");

    for (int t = 0; t < nT; t++) {
        if (t + 1 < nT) loadStage(t + 1, (t + 1) & 1);
        asm volatile("cp.async.commit_group;\n");
        asm volatile("cp.async.wait_group 1;\n");
        __syncthreads();

        const int st = t & 1;
#pragma unroll
        for (int ks = 0; ks < 2; ks++) {
            uint32_t a[4][4], b[4][4];
#pragma unroll
            for (int mi = 0; mi < 4; mi++) {
                uint32_t addr = smem_u32(
                    &As[st][wm * 64 + mi * 16 + (lane & 15)][ks * 16 + (lane >> 4) * 8]);
                asm volatile(
                    "ldmatrix.sync.aligned.m8n8.x4.shared.b16 {%0,%1,%2,%3}, [%4];"
                    : "=r"(a[mi][0]), "=r"(a[mi][1]), "=r"(a[mi][2]), "=r"(a[mi][3])
                    : "r"(addr));
            }
#pragma unroll
            for (int pi = 0; pi < 4; pi++) {
                uint32_t addr = smem_u32(
                    &Bs[st][ks * 16 + (lane & 7) + ((lane >> 3) & 1) * 8]
                       [wn * 64 + pi * 16 + (lane >> 4) * 8]);
                asm volatile(
                    "ldmatrix.sync.aligned.m8n8.x4.trans.shared.b16 {%0,%1,%2,%3}, [%4];"
                    : "=r"(b[pi][0]), "=r"(b[pi][1]), "=r"(b[pi][2]), "=r"(b[pi][3])
                    : "r"(addr));
            }
#pragma unroll
            for (int mi = 0; mi < 4; mi++)
#pragma unroll
                for (int ni = 0; ni < 8; ni++) {
                    uint32_t b0 = b[ni >> 1][(ni & 1) * 2];
                    uint32_t b1 = b[ni >> 1][(ni & 1) * 2 + 1];
                    asm volatile(
                        "mma.sync.aligned.m16n8k16.row.col.f32.f16.f16.f32 "
                        "{%0,%1,%2,%3}, {%4,%5,%6,%7}, {%8,%9}, {%0,%1,%2,%3};"
                        : "+f"(c[mi][ni][0]), "+f"(c[mi][ni][1]),
                          "+f"(c[mi][ni][2]), "+f"(c[mi][ni][3])
                        : "r"(a[mi][0]), "r"(a[mi][1]), "r"(a[mi][2]), "r"(a[mi][3]),
                          "r"(b0), "r"(b1));
                }
        }
        __syncthreads();
    }

    // epilogue
#pragma unroll
    for (int mi = 0; mi < 4; mi++) {
        const int row  = brow + wm * 64 + mi * 16 + (lane >> 2);
        const int row2 = row + 8;
        const float* ra = rowAdd ? rowAdd + (size_t)(row >> 4) * N : nullptr;
#pragma unroll
        for (int ni = 0; ni < 8; ni++) {
            const int col = bcol + wn * 64 + ni * 8 + (lane & 3) * 2;
            float v0 = c[mi][ni][0], v1 = c[mi][ni][1];
            float v2 = c[mi][ni][2], v3 = c[mi][ni][3];
            if (bias) {
                const float bb0 = bias[col], bb1 = bias[col + 1];
                v0 += bb0; v1 += bb1; v2 += bb0; v3 += bb1;
            }
            if (ra) {
                const float r0 = ra[col], r1 = ra[col + 1];
                v0 += r0; v1 += r1; v2 += r0; v3 += r1;
            }
            if (doRelu) {
                v0 = fmaxf(v0, 0.f); v1 = fmaxf(v1, 0.f);
                v2 = fmaxf(v2, 0.f); v3 = fmaxf(v3, 0.f);
            }
            if (Ch) {
                *(__half2*)&Ch[(size_t)row  * N + col] = __floats2half2_rn(v0, v1);
                *(__half2*)&Ch[(size_t)row2 * N + col] = __floats2half2_rn(v2, v3);
            } else {
                *(float2*)&Cf[(size_t)row  * N + col] = make_float2(v0, v1);
                *(float2*)&Cf[(size_t)row2 * N + col] = make_float2(v2, v3);
            }
        }
    }
}

// ---------------------------------------------------------------------------
// Weight packing fp32 -> fp16: Wcat=[W_pre|W_loc], then Wgcn, Wpost, W1, W2
// ---------------------------------------------------------------------------
__global__ void convW(const float* __restrict__ Wpre, const float* __restrict__ Wloc,
                      const float* __restrict__ Wgcn, const float* __restrict__ Wpost,
                      const float* __restrict__ W1, const float* __restrict__ W2,
                      __half* __restrict__ out)
{
    int idx = blockIdx.x * blockDim.x + threadIdx.x;
    if (idx >= WH_TOTAL) return;
    float v;
    if (idx < OFF_WGCN) {
        int k = idx / 384, j = idx % 384;
        v = (j < 128) ? Wpre[k * 128 + j] : Wloc[k * 256 + (j - 128)];
    }
    else if (idx < OFF_WPOST) v = Wgcn[idx - OFF_WGCN];
    else if (idx < OFF_W1)    v = Wpost[idx - OFF_WPOST];
    else if (idx < OFF_W2)    v = W1[idx - OFF_W1];
    else                      v = W2[idx - OFF_W2];
    out[idx] = __float2half_rn(v);
}

__global__ void fillBcat(const float* __restrict__ b_pre,
                         const float* __restrict__ b_loc, float* __restrict__ bcat)
{
    int i = threadIdx.x;
    bcat[i] = (i < 128) ? b_pre[i] : b_loc[i - 128];
}

// ---------------------------------------------------------------------------
// Mean over 16 agents, fp16 in (row stride s2 half2), fp16 out [S,128]
// ---------------------------------------------------------------------------
__global__ void mean16h(const __half2* __restrict__ x, __half2* __restrict__ xbar,
                        int S, int s2)
{
    int idx = blockIdx.x * blockDim.x + threadIdx.x;
    if (idx >= S * 64) return;
    int s = idx >> 6, cc = idx & 63;
    const __half2* p = x + (size_t)s * NAGENT * s2 + cc;
    float ax = 0.f, ay = 0.f;
#pragma unroll
    for (int a = 0; a < NAGENT; a++) {
        float2 v = __half22float2(p[(size_t)a * s2]);
        ax += v.x; ay += v.y;
    }
    xbar[(size_t)s * 64 + cc] = __floats2half2_rn(ax * (1.f / NAGENT), ay * (1.f / NAGENT));
}

// ---------------------------------------------------------------------------
// q[M,8] = z2[M,512](fp16) @ W3[512,8] + b3 (warp per row)
// ---------------------------------------------------------------------------
__global__ __launch_bounds__(256) void qgemm(
    const __half* __restrict__ z2, const float* __restrict__ W3,
    const float* __restrict__ b3, float* __restrict__ q, int M)
{
    __shared__ float W3s[F2 * NACT];
    for (int i = threadIdx.x; i < F2 * NACT; i += 256) W3s[i] = W3[i];
    __syncthreads();

    const int warp = threadIdx.x >> 5;
    const int lane = threadIdx.x & 31;
    const int row  = blockIdx.x * 8 + warp;
    if (row >= M) return;

    const __half2* zr = (const __half2*)(z2 + (size_t)row * F2);
    float acc[NACT] = {};
    for (int k2 = lane; k2 < F2 / 2; k2 += 32) {
        float2 z = __half22float2(zr[k2]);
        const float* w0 = &W3s[(2 * k2) * NACT];
#pragma unroll
        for (int n = 0; n < NACT; n++)
            acc[n] = fmaf(z.x, w0[n], fmaf(z.y, w0[NACT + n], acc[n]));
    }
#pragma unroll
    for (int n = 0; n < NACT; n++)
#pragma unroll
        for (int off = 16; off > 0; off >>= 1)
            acc[n] += __shfl_xor_sync(0xffffffff, acc[n], off);
    if (lane == 0) {
        float* qr = q + (size_t)row * NACT;
#pragma unroll
        for (int n = 0; n < NACT; n++) qr[n] = acc[n] + b3[n];
    }
}

// ---------------------------------------------------------------------------
extern "C" void kernel_launch(void* const* d_in, const int* in_sizes, int n_in,
                              void* d_out, int out_size)
{
    const float* obs    = (const float*)d_in[0];
    const float* W_pre  = (const float*)d_in[1];
    const float* b_pre  = (const float*)d_in[2];
    const float* W_gcn  = (const float*)d_in[3];
    const float* b_gcn  = (const float*)d_in[4];
    const float* W_post = (const float*)d_in[5];
    const float* b_post = (const float*)d_in[6];
    const float* W_loc  = (const float*)d_in[7];
    const float* b_loc  = (const float*)d_in[8];
    const float* W1     = (const float*)d_in[9];
    const float* b1     = (const float*)d_in[10];
    const float* W2     = (const float*)d_in[11];
    const float* b2     = (const float*)d_in[12];
    const float* W3     = (const float*)d_in[13];
    const float* b3     = (const float*)d_in[14];
    float* q = (float*)d_out;

    const int Bsz = in_sizes[0] / (NAGENT * OBS);   // 2048
    const int M   = Bsz * NAGENT;                   // 32768

    __half *wh, *xloc, *xbar, *s0, *s1, *gv, *z1, *z2;
    float *bcat, *G1;
    cudaGetSymbolAddress((void**)&wh,   g_wh);
    cudaGetSymbolAddress((void**)&bcat, g_bcat);
    cudaGetSymbolAddress((void**)&xloc, g_xloc);
    cudaGetSymbolAddress((void**)&xbar, g_xbar);
    cudaGetSymbolAddress((void**)&s0,   g_s0);
    cudaGetSymbolAddress((void**)&s1,   g_s1);
    cudaGetSymbolAddress((void**)&gv,   g_gv);
    cudaGetSymbolAddress((void**)&G1,   g_G1);
    cudaGetSymbolAddress((void**)&z1,   g_z1);
    cudaGetSymbolAddress((void**)&z2,   g_z2);

    convW<<<(WH_TOTAL + 255) / 256, 256>>>(W_pre, W_loc, W_gcn, W_post, W1, W2, wh);
    fillBcat<<<1, 384>>>(b_pre, b_loc, bcat);

    // 1) [x|loc] = relu(obs @ [W_pre|W_loc] + bcat)    [M,384], A fp32 on-the-fly
    hgemm<1><<<dim3(3, M / BM), 128>>>(obs, wh + OFF_WCAT, xloc, nullptr,
                                       M, 384, OBS, OBS, bcat, nullptr, 1);
    // 2) xbar = mean over agents of x                  [B,128]
    mean16h<<<(Bsz * 64 + 255) / 256, 256>>>((const __half2*)xloc, (__half2*)xbar,
                                             Bsz, 192);
    // 3) collapsed GCN chain (per-sample rows)
    hgemm<0><<<dim3(1, Bsz / BM), 128>>>(xbar, wh + OFF_WGCN, s0, nullptr,
                                         Bsz, HID, HID, HID, b_gcn, nullptr, 1);
    hgemm<0><<<dim3(1, Bsz / BM), 128>>>(s0, wh + OFF_WGCN + HID * HID, s1, nullptr,
                                         Bsz, HID, HID, HID, b_gcn + HID, nullptr, 1);
    hgemm<0><<<dim3(GE / BN, Bsz / BM), 128>>>(s1, wh + OFF_WPOST, gv, nullptr,
                                               Bsz, GE, HID, HID, b_post, nullptr, 1);
    // 4) G1 = g @ W1[:256,:] + b1 (fp32 out)           [B,512]
    hgemm<0><<<dim3(F1 / BN, Bsz / BM), 128>>>(gv, wh + OFF_W1, nullptr, G1,
                                               Bsz, F1, GE, GE, b1, nullptr, 0);
    // 5) z1 = relu(loc @ W1[256:,:] + G1[sample])      [M,512]
    hgemm<0><<<dim3(F1 / BN, M / BM), 128>>>(xloc + 128, wh + OFF_W1 + GE * F1,
                                             z1, nullptr, M, F1, LE, 384,
                                             nullptr, G1, 1);
    // 6) z2 = relu(z1 @ W2 + b2)                       [M,512]
    hgemm<0><<<dim3(F2 / BN, M / BM), 128>>>(z1, wh + OFF_W2, z2, nullptr,
                                             M, F2, F1, F1, b2, nullptr, 1);
    // 7) q = z2 @ W3 + b3                              [M,8]
    qgemm<<<M / 8, 256>>>(z2, W3, b3, q, M);
}

// round 6
// speedup vs baseline: 1.3487x; 1.3487x over previous
#include <cuda_runtime.h>
#include <cuda_fp16.h>
#include <cstdint>

#define OBS 128
#define NAGENT 16
#define HID 128
#define GE 256
#define LE 256
#define F1 512
#define F2 512
#define NACT 8
#define MAXB 2048
#define MAXM (MAXB * NAGENT)

// fp16 weight pack offsets (halves)
#define OFF_WCAT  0            // [128, 384] = [W_pre | W_loc]
#define OFF_WGCN  49152        // [2,128,128]
#define OFF_WPOST 81920        // [128,256]
#define OFF_W1    114688       // [512,512]
#define OFF_W2    376832       // [512,512]
#define WH_TOTAL  638976

__device__ __align__(16) __half g_wh[WH_TOTAL];
__device__ __align__(16) float  g_bcat[384];
__device__ __align__(16) __half g_xloc[MAXM * 384];   // [x | loc]
__device__ __align__(16) __half g_xbar[MAXB * HID];
__device__ __align__(16) __half g_s0[MAXB * HID];
__device__ __align__(16) __half g_s1[MAXB * HID];
__device__ __align__(16) __half g_gv[MAXB * GE];
__device__ __align__(16) float  g_G1[MAXB * F1];
__device__ __align__(16) __half g_z1[MAXM * F1];
__device__ __align__(16) float  g_qpart[4 * MAXM * NACT];

#define BM 128
#define BN 128
#define BK 64

// dynamic smem layout (halves):
//   stage st: A at st*17920,  rows 128 x 72 halves
//             B at st*17920 + 9216, rows 64 x 136 halves
// epilogue overlay: zs 128 x 136 halves (=17408), then W3s (float[1024])
#define A_ST   17920
#define A_RS   72
#define B_OFF  9216
#define B_RS   136
#define SMEMB  71680

__device__ __forceinline__ void cp16(uint32_t dst, const void* src) {
    asm volatile("cp.async.cg.shared.global [%0], [%1], 16;\n" ::"r"(dst), "l"(src));
}
__device__ __forceinline__ uint32_t smem_u32(const void* p) {
    return (uint32_t)__cvta_generic_to_shared(p);
}

// ---------------------------------------------------------------------------
// fp16 HMMA GEMM. AF32: A is fp32 converted inline. FUSE: 0 none,
// 1 = also produce xbar (mean over 16-row groups of cols 0..127, block x==0),
// 2 = don't write C; produce q_part[bx] = relu(tile) @ W3[bcol:bcol+128,:8].
// BM=BN=128, BK=64, 256 threads, 8 warps @ 64x32.
// ---------------------------------------------------------------------------
template <int AF32, int FUSE>
__global__ __launch_bounds__(256) void hgemm(
    const void* __restrict__ Ap, const __half* __restrict__ B,
    __half* __restrict__ Ch, float* __restrict__ Cf,
    int M, int N, int K, int lda,
    const float* __restrict__ bias, const float* __restrict__ rowAdd,
    int doRelu, __half* __restrict__ aux_h, const float* __restrict__ aux_f)
{
    extern __shared__ __half S[];

    const int tid  = threadIdx.x;
    const int lane = tid & 31;
    const int wid  = tid >> 5;
    const int wm   = wid >> 2;     // 0..1 (64-row slab)
    const int wn   = wid & 3;      // 0..3 (32-col slab)
    const int brow = blockIdx.y * BM;
    const int bcol = blockIdx.x * BN;

    const __half* Ah = (const __half*)Ap;
    const float*  Af = (const float*)Ap;

    float c[4][4][4];
#pragma unroll
    for (int i = 0; i < 4; i++)
#pragma unroll
        for (int j = 0; j < 4; j++)
#pragma unroll
            for (int e = 0; e < 4; e++) c[i][j][e] = 0.f;

    const int nT = K / BK;

    auto loadStage = [&](int t, int st) {
        const int k0 = t * BK;
        __half* As = S + st * A_ST;
        __half* Bs = S + st * A_ST + B_OFF;
        // A: 128 rows x 64 halves = 1024 chunks of 8 halves; 4/thread
#pragma unroll
        for (int j = 0; j < 4; j++) {
            const int ch = j * 256 + tid;
            const int r = ch >> 3, cc = (ch & 7) * 8;
            if (AF32) {
                const float4* s =
                    (const float4*)(Af + (size_t)(brow + r) * lda + k0 + cc);
                float4 v0 = s[0], v1 = s[1];
                __half2 h0 = __floats2half2_rn(v0.x, v0.y);
                __half2 h1 = __floats2half2_rn(v0.z, v0.w);
                __half2 h2 = __floats2half2_rn(v1.x, v1.y);
                __half2 h3 = __floats2half2_rn(v1.z, v1.w);
                uint4 u;
                u.x = *(uint32_t*)&h0; u.y = *(uint32_t*)&h1;
                u.z = *(uint32_t*)&h2; u.w = *(uint32_t*)&h3;
                *(uint4*)&As[r * A_RS + cc] = u;
            } else {
                cp16(smem_u32(&As[r * A_RS + cc]),
                     Ah + (size_t)(brow + r) * lda + k0 + cc);
            }
        }
        // B: 64 rows x 128 halves = 1024 chunks; 4/thread
#pragma unroll
        for (int j = 0; j < 4; j++) {
            const int ch = j * 256 + tid;
            const int r = ch >> 4, cc = (ch & 15) * 8;
            cp16(smem_u32(&Bs[r * B_RS + cc]),
                 B + (size_t)(k0 + r) * N + bcol + cc);
        }
    };

    loadStage(0, 0);
    asm volatile("cp.async.commit_group;\n");

    for (int t = 0; t < nT; t++) {
        if (t + 1 < nT) loadStage(t + 1, (t + 1) & 1);
        asm volatile("cp.async.commit_group;\n");
        asm volatile("cp.async.wait_group 1;\n");
        __syncthreads();

        const __half* As = S + (t & 1) * A_ST;
        const __half* Bs = S + (t & 1) * A_ST + B_OFF;
#pragma unroll
        for (int ks = 0; ks < 4; ks++) {
            uint32_t a[4][4], b[2][4];
#pragma unroll
            for (int mi = 0; mi < 4; mi++) {
                uint32_t addr = smem_u32(
                    &As[(wm * 64 + mi * 16 + (lane & 15)) * A_RS +
                        ks * 16 + (lane >> 4) * 8]);
                asm volatile(
                    "ldmatrix.sync.aligned.m8n8.x4.shared.b16 {%0,%1,%2,%3}, [%4];"
                    : "=r"(a[mi][0]), "=r"(a[mi][1]), "=r"(a[mi][2]), "=r"(a[mi][3])
                    : "r"(addr));
            }
#pragma unroll
            for (int pi = 0; pi < 2; pi++) {
                uint32_t addr = smem_u32(
                    &Bs[(ks * 16 + (lane & 7) + ((lane >> 3) & 1) * 8) * B_RS +
                        wn * 32 + pi * 16 + (lane >> 4) * 8]);
                asm volatile(
                    "ldmatrix.sync.aligned.m8n8.x4.trans.shared.b16 {%0,%1,%2,%3}, [%4];"
                    : "=r"(b[pi][0]), "=r"(b[pi][1]), "=r"(b[pi][2]), "=r"(b[pi][3])
                    : "r"(addr));
            }
#pragma unroll
            for (int mi = 0; mi < 4; mi++)
#pragma unroll
                for (int ni = 0; ni < 4; ni++) {
                    uint32_t b0 = b[ni >> 1][(ni & 1) * 2];
                    uint32_t b1 = b[ni >> 1][(ni & 1) * 2 + 1];
                    asm volatile(
                        "mma.sync.aligned.m16n8k16.row.col.f32.f16.f16.f32 "
                        "{%0,%1,%2,%3}, {%4,%5,%6,%7}, {%8,%9}, {%0,%1,%2,%3};"
                        : "+f"(c[mi][ni][0]), "+f"(c[mi][ni][1]),
                          "+f"(c[mi][ni][2]), "+f"(c[mi][ni][3])
                        : "r"(a[mi][0]), "r"(a[mi][1]), "r"(a[mi][2]), "r"(a[mi][3]),
                          "r"(b0), "r"(b1));
                }
        }
        __syncthreads();
    }

    const bool stage = (FUSE == 2) || (FUSE == 1 && blockIdx.x == 0);
    __half* zs = S;   // 128 x B_RS overlay (pipeline smem is dead now)

    // epilogue
#pragma unroll
    for (int mi = 0; mi < 4; mi++) {
        const int rl0 = wm * 64 + mi * 16 + (lane >> 2);
        const int row  = brow + rl0;
        const int row2 = row + 8;
        const float* ra = rowAdd ? rowAdd + (size_t)(row >> 4) * N : nullptr;
#pragma unroll
        for (int ni = 0; ni < 4; ni++) {
            const int cl  = wn * 32 + ni * 8 + (lane & 3) * 2;
            const int col = bcol + cl;
            float v0 = c[mi][ni][0], v1 = c[mi][ni][1];
            float v2 = c[mi][ni][2], v3 = c[mi][ni][3];
            if (bias) {
                const float bb0 = bias[col], bb1 = bias[col + 1];
                v0 += bb0; v1 += bb1; v2 += bb0; v3 += bb1;
            }
            if (ra) {
                const float r0 = ra[col], r1 = ra[col + 1];
                v0 += r0; v1 += r1; v2 += r0; v3 += r1;
            }
            if (doRelu) {
                v0 = fmaxf(v0, 0.f); v1 = fmaxf(v1, 0.f);
                v2 = fmaxf(v2, 0.f); v3 = fmaxf(v3, 0.f);
            }
            __half2 h01 = __floats2half2_rn(v0, v1);
            __half2 h23 = __floats2half2_rn(v2, v3);
            if (FUSE != 2) {
                if (Ch) {
                    *(__half2*)&Ch[(size_t)row  * N + col] = h01;
                    *(__half2*)&Ch[(size_t)row2 * N + col] = h23;
                } else {
                    *(float2*)&Cf[(size_t)row  * N + col] = make_float2(v0, v1);
                    *(float2*)&Cf[(size_t)row2 * N + col] = make_float2(v2, v3);
                }
            }
            if (stage) {
                *(__half2*)&zs[rl0 * B_RS + cl]       = h01;
                *(__half2*)&zs[(rl0 + 8) * B_RS + cl] = h23;
            }
        }
    }

    if (FUSE == 1 && blockIdx.x == 0) {
        // xbar: mean over 16-row groups of the 128x128 tile (cols 0..127)
        __syncthreads();
        const int s0 = brow >> 4;   // first sample of this tile
#pragma unroll
        for (int j = 0; j < 4; j++) {
            const int idx = j * 256 + tid;
            const int s = idx >> 7, cc = idx & 127;
            float acc = 0.f;
#pragma unroll
            for (int r = 0; r < 16; r++)
                acc += __half2float(zs[(s * 16 + r) * B_RS + cc]);
            aux_h[(size_t)(s0 + s) * 128 + cc] = __float2half_rn(acc * (1.f / 16.f));
        }
    }

    if (FUSE == 2) {
        // q_part[bx][row][0..7] = zs(row,:) . W3[bcol+ :, :]
        __syncthreads();
        float* W3s = (float*)(zs + 128 * B_RS);
        {
            const float4* src = (const float4*)(aux_f + (size_t)bcol * NACT);
            ((float4*)W3s)[tid] = src[tid];   // 256 float4 = 1024 floats
        }
        __syncthreads();
        const __half2* zs2 = (const __half2*)zs;
        float* qp = Cf + (size_t)blockIdx.x * M * NACT;
#pragma unroll
        for (int rr = 0; rr < 2; rr++) {
            const int rl = wid * 16 + rr * 8 + (lane >> 2);   // 8 rows x 4 lanes? no:
            (void)rl;
        }
        // each warp: 16 rows
        for (int rr = 0; rr < 16; rr++) {
            const int rl = wid * 16 + rr;
            float acc[NACT] = {};
#pragma unroll
            for (int it = 0; it < 2; it++) {
                const int k2 = it * 32 + lane;      // half2 index 0..63
                float2 z = __half22float2(zs2[rl * (B_RS / 2) + k2]);
                const float* w0 = &W3s[(2 * k2) * NACT];
#pragma unroll
                for (int n = 0; n < NACT; n++)
                    acc[n] = fmaf(z.x, w0[n], fmaf(z.y, w0[NACT + n], acc[n]));
            }
#pragma unroll
            for (int n = 0; n < NACT; n++)
#pragma unroll
                for (int off = 16; off > 0; off >>= 1)
                    acc[n] += __shfl_xor_sync(0xffffffff, acc[n], off);
            if (lane == 0) {
                float* o = qp + (size_t)(brow + rl) * NACT;
#pragma unroll
                for (int n = 0; n < NACT; n++) o[n] = acc[n];
            }
        }
    }
}

// ---------------------------------------------------------------------------
__global__ void convW(const float* __restrict__ Wpre, const float* __restrict__ Wloc,
                      const float* __restrict__ Wgcn, const float* __restrict__ Wpost,
                      const float* __restrict__ W1, const float* __restrict__ W2,
                      __half* __restrict__ out)
{
    int idx = blockIdx.x * blockDim.x + threadIdx.x;
    if (idx >= WH_TOTAL) return;
    float v;
    if (idx < OFF_WGCN) {
        int k = idx / 384, j = idx % 384;
        v = (j < 128) ? Wpre[k * 128 + j] : Wloc[k * 256 + (j - 128)];
    }
    else if (idx < OFF_WPOST) v = Wgcn[idx - OFF_WGCN];
    else if (idx < OFF_W1)    v = Wpost[idx - OFF_WPOST];
    else if (idx < OFF_W2)    v = W1[idx - OFF_W1];
    else                      v = W2[idx - OFF_W2];
    out[idx] = __float2half_rn(v);
}

__global__ void fillBcat(const float* __restrict__ b_pre,
                         const float* __restrict__ b_loc, float* __restrict__ bcat)
{
    int i = threadIdx.x;
    bcat[i] = (i < 128) ? b_pre[i] : b_loc[i - 128];
}

// q = sum of 4 q_part + b3
__global__ void qreduce(const float4* __restrict__ qp, const float* __restrict__ b3,
                        float4* __restrict__ q, int n4)
{
    int i = blockIdx.x * blockDim.x + threadIdx.x;
    if (i >= n4) return;
    const float4 b = ((const float4*)b3)[i & 1];
    float4 a0 = qp[i], a1 = qp[n4 + i], a2 = qp[2 * n4 + i], a3 = qp[3 * n4 + i];
    float4 r;
    r.x = a0.x + a1.x + a2.x + a3.x + b.x;
    r.y = a0.y + a1.y + a2.y + a3.y + b.y;
    r.z = a0.z + a1.z + a2.z + a3.z + b.z;
    r.w = a0.w + a1.w + a2.w + a3.w + b.w;
    q[i] = r;
}

// ---------------------------------------------------------------------------
extern "C" void kernel_launch(void* const* d_in, const int* in_sizes, int n_in,
                              void* d_out, int out_size)
{
    const float* obs    = (const float*)d_in[0];
    const float* W_pre  = (const float*)d_in[1];
    const float* b_pre  = (const float*)d_in[2];
    const float* W_gcn  = (const float*)d_in[3];
    const float* b_gcn  = (const float*)d_in[4];
    const float* W_post = (const float*)d_in[5];
    const float* b_post = (const float*)d_in[6];
    const float* W_loc  = (const float*)d_in[7];
    const float* b_loc  = (const float*)d_in[8];
    const float* W1     = (const float*)d_in[9];
    const float* b1     = (const float*)d_in[10];
    const float* W2     = (const float*)d_in[11];
    const float* b2     = (const float*)d_in[12];
    const float* W3     = (const float*)d_in[13];
    const float* b3     = (const float*)d_in[14];
    float* q = (float*)d_out;

    const int Bsz = in_sizes[0] / (NAGENT * OBS);   // 2048
    const int M   = Bsz * NAGENT;                   // 32768

    __half *wh, *xloc, *xbar, *s0, *s1, *gv, *z1;
    float *bcat, *G1, *qp;
    cudaGetSymbolAddress((void**)&wh,   g_wh);
    cudaGetSymbolAddress((void**)&bcat, g_bcat);
    cudaGetSymbolAddress((void**)&xloc, g_xloc);
    cudaGetSymbolAddress((void**)&xbar, g_xbar);
    cudaGetSymbolAddress((void**)&s0,   g_s0);
    cudaGetSymbolAddress((void**)&s1,   g_s1);
    cudaGetSymbolAddress((void**)&gv,   g_gv);
    cudaGetSymbolAddress((void**)&G1,   g_G1);
    cudaGetSymbolAddress((void**)&z1,   g_z1);
    cudaGetSymbolAddress((void**)&qp,   g_qpart);

    cudaFuncSetAttribute(hgemm<1, 1>, cudaFuncAttributeMaxDynamicSharedMemorySize, SMEMB);
    cudaFuncSetAttribute(hgemm<0, 0>, cudaFuncAttributeMaxDynamicSharedMemorySize, SMEMB);
    cudaFuncSetAttribute(hgemm<0, 2>, cudaFuncAttributeMaxDynamicSharedMemorySize, SMEMB);

    convW<<<(WH_TOTAL + 255) / 256, 256>>>(W_pre, W_loc, W_gcn, W_post, W1, W2, wh);
    fillBcat<<<1, 384>>>(b_pre, b_loc, bcat);

    // 1) [x|loc] = relu(obs @ [W_pre|W_loc] + bcat); block x==0 also emits xbar
    hgemm<1, 1><<<dim3(3, M / BM), 256, SMEMB>>>(obs, wh + OFF_WCAT, xloc, nullptr,
                                                 M, 384, OBS, OBS, bcat, nullptr, 1,
                                                 xbar, nullptr);
    // 2) collapsed GCN chain (per-sample rows)
    hgemm<0, 0><<<dim3(1, Bsz / BM), 256, SMEMB>>>(xbar, wh + OFF_WGCN, s0, nullptr,
                                                   Bsz, HID, HID, HID, b_gcn, nullptr, 1,
                                                   nullptr, nullptr);
    hgemm<0, 0><<<dim3(1, Bsz / BM), 256, SMEMB>>>(s0, wh + OFF_WGCN + HID * HID, s1,
                                                   nullptr, Bsz, HID, HID, HID,
                                                   b_gcn + HID, nullptr, 1,
                                                   nullptr, nullptr);
    hgemm<0, 0><<<dim3(GE / BN, Bsz / BM), 256, SMEMB>>>(s1, wh + OFF_WPOST, gv, nullptr,
                                                         Bsz, GE, HID, HID, b_post,
                                                         nullptr, 1, nullptr, nullptr);
    // 3) G1 = g @ W1[:256,:] + b1 (fp32 out)
    hgemm<0, 0><<<dim3(F1 / BN, Bsz / BM), 256, SMEMB>>>(gv, wh + OFF_W1, nullptr, G1,
                                                         Bsz, F1, GE, GE, b1, nullptr, 0,
                                                         nullptr, nullptr);
    // 4) z1 = relu(loc @ W1[256:,:] + G1[sample])
    hgemm<0, 0><<<dim3(F1 / BN, M / BM), 256, SMEMB>>>(xloc + 128, wh + OFF_W1 + GE * F1,
                                                       z1, nullptr, M, F1, LE, 384,
                                                       nullptr, G1, 1, nullptr, nullptr);
    // 5) fused z2+q: q_part[bx] = relu(z1 @ W2 + b2)[:, bx*128:+128] @ W3-slice
    hgemm<0, 2><<<dim3(F2 / BN, M / BM), 256, SMEMB>>>(z1, wh + OFF_W2, nullptr, qp,
                                                       M, F2, F1, F1, b2, nullptr, 1,
                                                       nullptr, W3);
    // 6) q = sum(q_part) + b3
    qreduce<<<(M * NACT / 4 + 255) / 256, 256>>>((const float4*)qp, b3, (float4*)q,
                                                 M * NACT / 4);
}